// round 1
// baseline (speedup 1.0000x reference)
#include <cuda_runtime.h>
#include <cuda_bf16.h>
#include <cstdint>

// Problem constants
#define NN_NODES 32768
#define E_MOL    131072
#define E_PRO    196608
#define F_MOL    78
#define F_PRO    54
#define HID      512
#define OUT_D    128
#define LAYERS   3

// ---------------- scratch (device globals; no allocation allowed) -----------
__device__ float g_h0m [NN_NODES * HID];
__device__ float g_prvm[NN_NODES * HID];
__device__ float g_h0p [NN_NODES * HID];
__device__ float g_prvp[NN_NODES * HID];
__device__ float g_supp[NN_NODES * HID];
__device__ float g_cat [NN_NODES * 256];
__device__ float g_fc1 [NN_NODES * 1024];
__device__ float g_fc2 [NN_NODES * 512];

__device__ int   g_cnt [NN_NODES];
__device__ int   g_cur [NN_NODES];
__device__ int   g_offm[NN_NODES + 1];
__device__ int   g_offp[NN_NODES + 1];
__device__ int   g_cscm[E_MOL];
__device__ int   g_cscp[E_PRO];
__device__ float g_dism[NN_NODES];
__device__ float g_disp[NN_NODES];

// ---------------- small helper kernels --------------------------------------
__global__ void zero_i_k(int* p, int n) {
    int i = blockIdx.x * blockDim.x + threadIdx.x;
    if (i < n) p[i] = 0;
}

__global__ void count_k(const int* __restrict__ col, int E, int* __restrict__ cnt) {
    int e = blockIdx.x * blockDim.x + threadIdx.x;
    if (e < E) atomicAdd(&cnt[col[e]], 1);
}

// single-block scan over NN_NODES counts -> offsets, cursor copy, dis = rsqrt(cnt+1)
__global__ void scan_k(const int* __restrict__ cnt, int* __restrict__ offs,
                       int* __restrict__ cur, float* __restrict__ dis, int n) {
    __shared__ int sh[1024];
    int t = threadIdx.x;
    int per = n >> 10;           // 32
    int base = t * per;
    int s = 0;
    for (int j = 0; j < per; j++) s += cnt[base + j];
    sh[t] = s;
    __syncthreads();
    for (int off = 1; off < 1024; off <<= 1) {
        int v = (t >= off) ? sh[t - off] : 0;
        __syncthreads();
        sh[t] += v;
        __syncthreads();
    }
    int run = sh[t] - s;         // exclusive prefix of this chunk
    for (int j = 0; j < per; j++) {
        int c = cnt[base + j];
        offs[base + j] = run;
        cur[base + j]  = run;
        dis[base + j]  = rsqrtf((float)(c + 1));
        run += c;
    }
    if (t == 1023) offs[n] = run;
}

__global__ void scatter_k(const int* __restrict__ row, const int* __restrict__ col,
                          int E, int* __restrict__ cur, int* __restrict__ src) {
    int e = blockIdx.x * blockDim.x + threadIdx.x;
    if (e < E) {
        int c = col[e];
        int p = atomicAdd(&cur[c], 1);
        src[p] = row[e];
    }
}

// ---------------- SpMM + support fuse ---------------------------------------
// support[i] = 0.8 * ( dis_i^2*prev[i] + sum_e dis_i*dis_src*prev[src] ) + 0.2*h0[i]
__global__ void spmm_support_k(const float* __restrict__ prev, const float* __restrict__ h0,
                               float* __restrict__ sup,
                               const int* __restrict__ offs, const int* __restrict__ srcs,
                               const float* __restrict__ dis) {
    int i = blockIdx.x;          // node
    int t = threadIdx.x;         // 128 threads, one float4 each (HID=512)
    const float4* pv = (const float4*)prev;
    float di = dis[i];
    float4 p = pv[(size_t)i * 128 + t];
    float self = di * di;
    float4 acc = make_float4(self * p.x, self * p.y, self * p.z, self * p.w);
    int e0 = offs[i], e1 = offs[i + 1];
    for (int e = e0; e < e1; e++) {
        int s = srcs[e];
        float w = di * dis[s];
        float4 q = pv[(size_t)s * 128 + t];
        acc.x += w * q.x; acc.y += w * q.y; acc.z += w * q.z; acc.w += w * q.w;
    }
    float4 h = ((const float4*)h0)[(size_t)i * 128 + t];
    float4 o;
    o.x = 0.8f * acc.x + 0.2f * h.x;
    o.y = 0.8f * acc.y + 0.2f * h.y;
    o.z = 0.8f * acc.z + 0.2f * h.z;
    o.w = 0.8f * acc.w + 0.2f * h.w;
    ((float4*)sup)[(size_t)i * 128 + t] = o;
}

// ---------------- TF32 tensor-core GEMM --------------------------------------
// C = A[M,K] * B[K,N]   (A ld==K, B ld==N)
// MODE 0: out = relu(acc + bias[n]); optional dual write to out2
// MODE 1: out = relu(acc + Csup[m,n]) + out[m,n]   (in-place residual; out==prev)
// MODE 2: out = acc + bias[n]   (strided output: ldo/ocol)
#define TBM 128
#define TBN 128
#define TBK 32

__device__ __forceinline__ uint32_t f2tf(float f) {
    uint32_t u;
    asm("cvt.rna.tf32.f32 %0, %1;" : "=r"(u) : "f"(f));
    return u;
}

__device__ __forceinline__ void mma_tf32(float* c, const uint32_t* a, const uint32_t* b) {
    asm volatile(
        "mma.sync.aligned.m16n8k8.row.col.f32.tf32.tf32.f32 "
        "{%0,%1,%2,%3}, {%4,%5,%6,%7}, {%8,%9}, {%0,%1,%2,%3};"
        : "+f"(c[0]), "+f"(c[1]), "+f"(c[2]), "+f"(c[3])
        : "r"(a[0]), "r"(a[1]), "r"(a[2]), "r"(a[3]), "r"(b[0]), "r"(b[1]));
}

template <int MODE>
__global__ __launch_bounds__(256)
void gemm_tf32_k(const float* __restrict__ A, const float* __restrict__ B,
                 const float* __restrict__ bias, const float* __restrict__ Csup,
                 float* __restrict__ out, float* __restrict__ out2,
                 int M, int Nn, int K, int ldo, int ocol) {
    __shared__ uint32_t sA[TBM][TBK + 4];
    __shared__ uint32_t sB[TBK][TBN + 4];

    int tid = threadIdx.x;
    int bm = blockIdx.y * TBM;
    int bn = blockIdx.x * TBN;
    int warp = tid >> 5, lane = tid & 31;
    int wm = (warp >> 2) * 64;   // warp row offset in tile (2 warps along M)
    int wn = (warp & 3) * 32;    // warp col offset (4 warps along N)
    int g = lane >> 2, tig = lane & 3;

    float acc[4][4][4];
#pragma unroll
    for (int mi = 0; mi < 4; mi++)
#pragma unroll
        for (int ni = 0; ni < 4; ni++)
#pragma unroll
            for (int e = 0; e < 4; e++) acc[mi][ni][e] = 0.f;

    int nk = (K + TBK - 1) / TBK;
    for (int kt = 0; kt < nk; kt++) {
        int k0 = kt * TBK;
        // A tile: 128x32 scalars (K may be 78/54: predicate)
#pragma unroll
        for (int j = 0; j < 16; j++) {
            int e = j * 256 + tid;
            int r = e >> 5, c = e & 31;
            int gk = k0 + c;
            float v = (gk < K) ? A[(size_t)(bm + r) * K + gk] : 0.f;
            sA[r][c] = f2tf(v);
        }
        // B tile: 32x128, float4 (N always %4)
#pragma unroll
        for (int j = 0; j < 4; j++) {
            int f = j * 256 + tid;
            int r = f >> 5, c4 = (f & 31) * 4;
            float4 v = make_float4(0.f, 0.f, 0.f, 0.f);
            if (k0 + r < K) v = *(const float4*)&B[(size_t)(k0 + r) * Nn + bn + c4];
            sB[r][c4 + 0] = f2tf(v.x);
            sB[r][c4 + 1] = f2tf(v.y);
            sB[r][c4 + 2] = f2tf(v.z);
            sB[r][c4 + 3] = f2tf(v.w);
        }
        __syncthreads();
#pragma unroll
        for (int ks = 0; ks < 4; ks++) {
            int kk = ks * 8;
            uint32_t af[4][4], bf[4][2];
#pragma unroll
            for (int mi = 0; mi < 4; mi++) {
                int r0 = wm + mi * 16;
                af[mi][0] = sA[r0 + g][kk + tig];
                af[mi][1] = sA[r0 + g + 8][kk + tig];
                af[mi][2] = sA[r0 + g][kk + tig + 4];
                af[mi][3] = sA[r0 + g + 8][kk + tig + 4];
            }
#pragma unroll
            for (int ni = 0; ni < 4; ni++) {
                bf[ni][0] = sB[kk + tig][wn + ni * 8 + g];
                bf[ni][1] = sB[kk + tig + 4][wn + ni * 8 + g];
            }
#pragma unroll
            for (int mi = 0; mi < 4; mi++)
#pragma unroll
                for (int ni = 0; ni < 4; ni++) mma_tf32(acc[mi][ni], af[mi], bf[ni]);
        }
        __syncthreads();
    }

    // epilogue
#pragma unroll
    for (int mi = 0; mi < 4; mi++)
#pragma unroll
        for (int ni = 0; ni < 4; ni++) {
            int r = bm + wm + mi * 16 + g;
            int c = bn + wn + ni * 8 + 2 * tig;
#pragma unroll
            for (int e = 0; e < 4; e++) {
                int rr = r + ((e >= 2) ? 8 : 0);
                int cc = c + (e & 1);
                float v = acc[mi][ni][e];
                if (MODE == 0 || MODE == 2) {
                    v += bias[cc];
                    if (MODE == 0) v = fmaxf(v, 0.f);
                    size_t idx = (size_t)rr * ldo + ocol + cc;
                    out[idx] = v;
                    if (out2) out2[idx] = v;
                } else {  // MODE 1: relu(acc + support) + prev, in-place on prev
                    size_t idx = (size_t)rr * Nn + cc;
                    v += Csup[idx];
                    v = fmaxf(v, 0.f);
                    v += out[idx];
                    out[idx] = v;
                }
            }
        }
}

// ---------------- final GEMV: out[m] = fc2[m,:] . w_o + b_o ------------------
__global__ void gemv_k(const float* __restrict__ X, const float* __restrict__ w,
                       const float* __restrict__ b, float* __restrict__ out) {
    int row = blockIdx.x * 4 + (threadIdx.x >> 5);
    int lane = threadIdx.x & 31;
    const float* x = X + (size_t)row * 512;
    float s = 0.f;
#pragma unroll
    for (int j = 0; j < 16; j++) s += x[lane + j * 32] * w[lane + j * 32];
#pragma unroll
    for (int o = 16; o > 0; o >>= 1) s += __shfl_xor_sync(0xFFFFFFFFu, s, o);
    if (lane == 0) out[row] = s + b[0];
}

// ---------------- launch ------------------------------------------------------
static void* sym(const void* s) {
    void* p = nullptr;
    cudaGetSymbolAddress(&p, (const void*)s);
    return p;
}

extern "C" void kernel_launch(void* const* d_in, const int* in_sizes, int n_in,
                              void* d_out, int out_size) {
    const float* mol_x     = (const float*)d_in[0];
    const int*   mol_ei    = (const int*)d_in[1];
    const float* pro_x     = (const float*)d_in[2];
    const int*   pro_ei    = (const int*)d_in[3];
    const float* mol_w_in  = (const float*)d_in[4];
    const float* mol_b_in  = (const float*)d_in[5];
    const float* mol_ws    = (const float*)d_in[6];
    const float* mol_w_out = (const float*)d_in[7];
    const float* mol_b_out = (const float*)d_in[8];
    const float* pro_w_in  = (const float*)d_in[9];
    const float* pro_b_in  = (const float*)d_in[10];
    const float* pro_ws    = (const float*)d_in[11];
    const float* pro_w_out = (const float*)d_in[12];
    const float* pro_b_out = (const float*)d_in[13];
    const float* w_fc1     = (const float*)d_in[14];
    const float* b_fc1     = (const float*)d_in[15];
    const float* w_fc2     = (const float*)d_in[16];
    const float* b_fc2     = (const float*)d_in[17];
    const float* w_o       = (const float*)d_in[18];
    const float* b_o       = (const float*)d_in[19];
    float* out = (float*)d_out;

    float* h0m  = (float*)sym(g_h0m);
    float* prvm = (float*)sym(g_prvm);
    float* h0p  = (float*)sym(g_h0p);
    float* prvp = (float*)sym(g_prvp);
    float* supp = (float*)sym(g_supp);
    float* cat  = (float*)sym(g_cat);
    float* fc1  = (float*)sym(g_fc1);
    float* fc2  = (float*)sym(g_fc2);
    int*   cnt  = (int*)sym(g_cnt);
    int*   cur  = (int*)sym(g_cur);
    int*   offm = (int*)sym(g_offm);
    int*   offp = (int*)sym(g_offp);
    int*   cscm = (int*)sym(g_cscm);
    int*   cscp = (int*)sym(g_cscp);
    float* dism = (float*)sym(g_dism);
    float* disp = (float*)sym(g_disp);

    const int N = NN_NODES;

    // ---- CSC build: mol ----
    zero_i_k<<<(N + 255) / 256, 256>>>(cnt, N);
    count_k<<<(E_MOL + 255) / 256, 256>>>(mol_ei + E_MOL, E_MOL, cnt);
    scan_k<<<1, 1024>>>(cnt, offm, cur, dism, N);
    scatter_k<<<(E_MOL + 255) / 256, 256>>>(mol_ei, mol_ei + E_MOL, E_MOL, cur, cscm);
    // ---- CSC build: pro ----
    zero_i_k<<<(N + 255) / 256, 256>>>(cnt, N);
    count_k<<<(E_PRO + 255) / 256, 256>>>(pro_ei + E_PRO, E_PRO, cnt);
    scan_k<<<1, 1024>>>(cnt, offp, cur, disp, N);
    scatter_k<<<(E_PRO + 255) / 256, 256>>>(pro_ei, pro_ei + E_PRO, E_PRO, cur, cscp);

    // ---- input projections: h = relu(x W + b), dual-write h0 and prev ----
    {
        dim3 grid(HID / TBN, N / TBM);
        gemm_tf32_k<0><<<grid, 256>>>(mol_x, mol_w_in, mol_b_in, nullptr,
                                      h0m, prvm, N, HID, F_MOL, HID, 0);
        gemm_tf32_k<0><<<grid, 256>>>(pro_x, pro_w_in, pro_b_in, nullptr,
                                      h0p, prvp, N, HID, F_PRO, HID, 0);
    }

    // ---- GCNII layers ----
    dim3 gridL(HID / TBN, N / TBM);
    for (int l = 0; l < LAYERS; l++) {
        spmm_support_k<<<N, 128>>>(prvm, h0m, supp, offm, cscm, dism);
        gemm_tf32_k<1><<<gridL, 256>>>(supp, mol_ws + (size_t)l * HID * HID, nullptr,
                                       supp, prvm, nullptr, N, HID, HID, HID, 0);
    }
    for (int l = 0; l < LAYERS; l++) {
        spmm_support_k<<<N, 128>>>(prvp, h0p, supp, offp, cscp, disp);
        gemm_tf32_k<1><<<gridL, 256>>>(supp, pro_ws + (size_t)l * HID * HID, nullptr,
                                       supp, prvp, nullptr, N, HID, HID, HID, 0);
    }

    // ---- output projections into concat buffer [N, 256] ----
    {
        dim3 grid(OUT_D / TBN, N / TBM);
        gemm_tf32_k<2><<<grid, 256>>>(prvm, mol_w_out, mol_b_out, nullptr,
                                      cat, nullptr, N, OUT_D, HID, 256, 0);
        gemm_tf32_k<2><<<grid, 256>>>(prvp, pro_w_out, pro_b_out, nullptr,
                                      cat, nullptr, N, OUT_D, HID, 256, OUT_D);
    }

    // ---- MLP head ----
    {
        dim3 grid(1024 / TBN, N / TBM);
        gemm_tf32_k<0><<<grid, 256>>>(cat, w_fc1, b_fc1, nullptr,
                                      fc1, nullptr, N, 1024, 256, 1024, 0);
    }
    {
        dim3 grid(512 / TBN, N / TBM);
        gemm_tf32_k<0><<<grid, 256>>>(fc1, w_fc2, b_fc2, nullptr,
                                      fc2, nullptr, N, 512, 1024, 512, 0);
    }
    gemv_k<<<N / 4, 128>>>(fc2, w_o, b_o, out);
}

// round 2
// speedup vs baseline: 1.5453x; 1.5453x over previous
#include <cuda_runtime.h>
#include <cuda_bf16.h>
#include <cstdint>

// Problem constants
#define NN_NODES 32768
#define E_MOL    131072
#define E_PRO    196608
#define HID      512
#define OUT_D    128
#define LAYERS   3

// padded K dims for input projections
#define KM_PAD 96   // 78 -> 96
#define KP_PAD 64   // 54 -> 64

// ---------------- scratch (device globals; no allocation allowed) -----------
__device__ float g_h0m [NN_NODES * HID];
__device__ float g_prvm[NN_NODES * HID];
__device__ float g_h0p [NN_NODES * HID];
__device__ float g_prvp[NN_NODES * HID];
__device__ float g_supp[NN_NODES * HID];
__device__ float g_cat [NN_NODES * 256];
__device__ float g_fc1 [NN_NODES * 1024];
__device__ float g_fc2 [NN_NODES * 512];
__device__ float g_xm  [NN_NODES * KM_PAD];
__device__ float g_xp  [NN_NODES * KP_PAD];
__device__ float g_wts [2600000];          // rounded weights

// rounded-weight buffer offsets
#define WIN_M  0
#define WIN_P  49152
#define WS_M   81920
#define WS_P   868352
#define WOUT_M 1654784
#define WOUT_P 1720320
#define WFC1   1785856
#define WFC2   2048000

__device__ int   g_cnt [NN_NODES];
__device__ int   g_cur [NN_NODES];
__device__ int   g_offm[NN_NODES + 1];
__device__ int   g_offp[NN_NODES + 1];
__device__ int   g_cscm[E_MOL];
__device__ int   g_cscp[E_PRO];
__device__ float g_dism[NN_NODES];
__device__ float g_disp[NN_NODES];

// ---------------- helpers ----------------------------------------------------
__device__ __forceinline__ float tf32r(float f) {
    uint32_t u;
    asm("cvt.rna.tf32.f32 %0, %1;" : "=r"(u) : "f"(f));
    return __uint_as_float(u);
}

__global__ void zero_i_k(int* p, int n) {
    int i = blockIdx.x * blockDim.x + threadIdx.x;
    if (i < n) p[i] = 0;
}

__global__ void count_k(const int* __restrict__ col, int E, int* __restrict__ cnt) {
    int e = blockIdx.x * blockDim.x + threadIdx.x;
    if (e < E) atomicAdd(&cnt[col[e]], 1);
}

__global__ void scan_k(const int* __restrict__ cnt, int* __restrict__ offs,
                       int* __restrict__ cur, float* __restrict__ dis, int n) {
    __shared__ int sh[1024];
    int t = threadIdx.x;
    int per = n >> 10;
    int base = t * per;
    int s = 0;
    for (int j = 0; j < per; j++) s += cnt[base + j];
    sh[t] = s;
    __syncthreads();
    for (int off = 1; off < 1024; off <<= 1) {
        int v = (t >= off) ? sh[t - off] : 0;
        __syncthreads();
        sh[t] += v;
        __syncthreads();
    }
    int run = sh[t] - s;
    for (int j = 0; j < per; j++) {
        int c = cnt[base + j];
        offs[base + j] = run;
        cur[base + j]  = run;
        dis[base + j]  = rsqrtf((float)(c + 1));
        run += c;
    }
    if (t == 1023) offs[n] = run;
}

__global__ void scatter_k(const int* __restrict__ row, const int* __restrict__ col,
                          int E, int* __restrict__ cur, int* __restrict__ src) {
    int e = blockIdx.x * blockDim.x + threadIdx.x;
    if (e < E) {
        int c = col[e];
        int p = atomicAdd(&cur[c], 1);
        src[p] = row[e];
    }
}

// pad+round: out[r,c] = (r<rows_in && c<cin) ? tf32(in[r,c]) : 0
__global__ void padround_k(const float* __restrict__ in, float* __restrict__ out,
                           int rows_in, int cin, int rows_out, int cout) {
    int i = blockIdx.x * blockDim.x + threadIdx.x;
    int total = rows_out * cout;
    if (i >= total) return;
    int r = i / cout, c = i - r * cout;
    float v = 0.f;
    if (r < rows_in && c < cin) v = tf32r(in[r * cin + c]);
    out[i] = v;
}

// ---------------- SpMM + support fuse (writes tf32-rounded output) -----------
__global__ void spmm_support_k(const float* __restrict__ prev, const float* __restrict__ h0,
                               float* __restrict__ sup,
                               const int* __restrict__ offs, const int* __restrict__ srcs,
                               const float* __restrict__ dis) {
    int i = blockIdx.x;
    int t = threadIdx.x;
    const float4* pv = (const float4*)prev;
    float di = dis[i];
    float4 p = pv[(size_t)i * 128 + t];
    float self = di * di;
    float4 acc = make_float4(self * p.x, self * p.y, self * p.z, self * p.w);
    int e0 = offs[i], e1 = offs[i + 1];
    for (int e = e0; e < e1; e++) {
        int s = srcs[e];
        float w = di * dis[s];
        float4 q = pv[(size_t)s * 128 + t];
        acc.x += w * q.x; acc.y += w * q.y; acc.z += w * q.z; acc.w += w * q.w;
    }
    float4 h = ((const float4*)h0)[(size_t)i * 128 + t];
    float4 o;
    o.x = tf32r(0.8f * acc.x + 0.2f * h.x);
    o.y = tf32r(0.8f * acc.y + 0.2f * h.y);
    o.z = tf32r(0.8f * acc.z + 0.2f * h.z);
    o.w = tf32r(0.8f * acc.w + 0.2f * h.w);
    ((float4*)sup)[(size_t)i * 128 + t] = o;
}

// ---------------- TF32 pipelined tensor-core GEMM -----------------------------
// All inputs pre-rounded to tf32. A[M,K] (ld=lda), B[K,N] (ld=ldb). K%32==0.
// MODE 0: out = relu(acc+bias); optional dual write out2
// MODE 1: out = relu(acc + Csup) + out   (in-place residual, ld=ldo)
// MODE 2: out = acc + bias               (strided: ldo/ocol)
#define TBM 128
#define TBN 128
#define TBK 32
#define SA_ELEMS (128 * 36)   // 4608
#define SB_ELEMS (32 * 132)   // 4224
#define SMEM_BYTES ((2 * SA_ELEMS + 2 * SB_ELEMS) * 4)  // 70656

__device__ __forceinline__ void cp16(uint32_t s, const float* g) {
    asm volatile("cp.async.cg.shared.global [%0], [%1], 16;" :: "r"(s), "l"(g));
}

__device__ __forceinline__ void mma_tf32(float* c, const uint32_t* a, const uint32_t* b) {
    asm volatile(
        "mma.sync.aligned.m16n8k8.row.col.f32.tf32.tf32.f32 "
        "{%0,%1,%2,%3}, {%4,%5,%6,%7}, {%8,%9}, {%0,%1,%2,%3};"
        : "+f"(c[0]), "+f"(c[1]), "+f"(c[2]), "+f"(c[3])
        : "r"(a[0]), "r"(a[1]), "r"(a[2]), "r"(a[3]), "r"(b[0]), "r"(b[1]));
}

template <int MODE, bool ROUND>
__global__ __launch_bounds__(256, 2)
void gemm_tf32_k(const float* __restrict__ A, int lda,
                 const float* __restrict__ B, int ldb,
                 const float* __restrict__ bias, const float* __restrict__ Csup,
                 float* __restrict__ out, float* __restrict__ out2,
                 int K, int ldo, int ocol) {
    extern __shared__ float smem[];
    uint32_t smem_u = (uint32_t)__cvta_generic_to_shared(smem);

    int tid = threadIdx.x;
    int bm = blockIdx.y * TBM;
    int bn = blockIdx.x * TBN;
    int warp = tid >> 5, lane = tid & 31;
    int wm = (warp >> 2) * 64;
    int wn = (warp & 3) * 32;
    int g = lane >> 2, tig = lane & 3;

    float acc[4][4][4];
#pragma unroll
    for (int mi = 0; mi < 4; mi++)
#pragma unroll
        for (int ni = 0; ni < 4; ni++)
#pragma unroll
            for (int e = 0; e < 4; e++) acc[mi][ni][e] = 0.f;

    auto load_tile = [&](int kt, int buf) {
        int k0 = kt * TBK;
        uint32_t sa = smem_u + (buf * SA_ELEMS) * 4;
        uint32_t sb = smem_u + ((2 * SA_ELEMS) + buf * SB_ELEMS) * 4;
#pragma unroll
        for (int j = 0; j < 4; j++) {
            int idx = j * 256 + tid;
            int r = idx >> 3, c4 = (idx & 7) * 4;
            cp16(sa + (r * 36 + c4) * 4, A + (size_t)(bm + r) * lda + k0 + c4);
        }
#pragma unroll
        for (int j = 0; j < 4; j++) {
            int idx = j * 256 + tid;
            int r = idx >> 5, c4 = (idx & 31) * 4;
            cp16(sb + (r * 132 + c4) * 4, B + (size_t)(k0 + r) * ldb + bn + c4);
        }
        asm volatile("cp.async.commit_group;");
    };

    int nk = K >> 5;
    load_tile(0, 0);
    int buf = 0;
    for (int kt = 0; kt < nk; kt++) {
        if (kt + 1 < nk) {
            load_tile(kt + 1, buf ^ 1);
            asm volatile("cp.async.wait_group 1;");
        } else {
            asm volatile("cp.async.wait_group 0;");
        }
        __syncthreads();

        const float* sAb = smem + buf * SA_ELEMS;
        const float* sBb = smem + 2 * SA_ELEMS + buf * SB_ELEMS;
#pragma unroll
        for (int ks = 0; ks < 4; ks++) {
            int kk = ks * 8;
            uint32_t af[4][4], bf[4][2];
#pragma unroll
            for (int mi = 0; mi < 4; mi++) {
                int r0 = wm + mi * 16;
                af[mi][0] = __float_as_uint(sAb[(r0 + g) * 36 + kk + tig]);
                af[mi][1] = __float_as_uint(sAb[(r0 + g + 8) * 36 + kk + tig]);
                af[mi][2] = __float_as_uint(sAb[(r0 + g) * 36 + kk + tig + 4]);
                af[mi][3] = __float_as_uint(sAb[(r0 + g + 8) * 36 + kk + tig + 4]);
            }
#pragma unroll
            for (int ni = 0; ni < 4; ni++) {
                int c = wn + ni * 8 + g;
                bf[ni][0] = __float_as_uint(sBb[(kk + tig) * 132 + c]);
                bf[ni][1] = __float_as_uint(sBb[(kk + tig + 4) * 132 + c]);
            }
#pragma unroll
            for (int mi = 0; mi < 4; mi++)
#pragma unroll
                for (int ni = 0; ni < 4; ni++) mma_tf32(acc[mi][ni], af[mi], bf[ni]);
        }
        __syncthreads();
        buf ^= 1;
    }

    // epilogue
#pragma unroll
    for (int mi = 0; mi < 4; mi++)
#pragma unroll
        for (int ni = 0; ni < 4; ni++) {
            int r = bm + wm + mi * 16 + g;
            int c = bn + wn + ni * 8 + 2 * tig;
#pragma unroll
            for (int e = 0; e < 4; e++) {
                int rr = r + ((e >= 2) ? 8 : 0);
                int cc = c + (e & 1);
                float v = acc[mi][ni][e];
                if (MODE == 0 || MODE == 2) {
                    v += bias[cc];
                    if (MODE == 0) v = fmaxf(v, 0.f);
                    if (ROUND) v = tf32r(v);
                    size_t idx = (size_t)rr * ldo + ocol + cc;
                    out[idx] = v;
                    if (out2) out2[idx] = v;
                } else {  // MODE 1: relu(acc + support) + prev, in-place on prev
                    size_t idx = (size_t)rr * ldo + cc;
                    v += Csup[idx];
                    v = fmaxf(v, 0.f);
                    v += out[idx];
                    if (ROUND) v = tf32r(v);
                    out[idx] = v;
                }
            }
        }
}

// ---------------- final GEMV: out[m] = fc2[m,:] . w_o + b_o ------------------
__global__ void gemv_k(const float* __restrict__ X, const float* __restrict__ w,
                       const float* __restrict__ b, float* __restrict__ out) {
    int row = blockIdx.x * 4 + (threadIdx.x >> 5);
    int lane = threadIdx.x & 31;
    const float* x = X + (size_t)row * 512;
    float s = 0.f;
#pragma unroll
    for (int j = 0; j < 16; j++) s += x[lane + j * 32] * w[lane + j * 32];
#pragma unroll
    for (int o = 16; o > 0; o >>= 1) s += __shfl_xor_sync(0xFFFFFFFFu, s, o);
    if (lane == 0) out[row] = s + b[0];
}

// ---------------- launch ------------------------------------------------------
static void* sym(const void* s) {
    void* p = nullptr;
    cudaGetSymbolAddress(&p, (const void*)s);
    return p;
}

extern "C" void kernel_launch(void* const* d_in, const int* in_sizes, int n_in,
                              void* d_out, int out_size) {
    const float* mol_x     = (const float*)d_in[0];
    const int*   mol_ei    = (const int*)d_in[1];
    const float* pro_x     = (const float*)d_in[2];
    const int*   pro_ei    = (const int*)d_in[3];
    const float* mol_w_in  = (const float*)d_in[4];
    const float* mol_b_in  = (const float*)d_in[5];
    const float* mol_ws    = (const float*)d_in[6];
    const float* mol_w_out = (const float*)d_in[7];
    const float* mol_b_out = (const float*)d_in[8];
    const float* pro_w_in  = (const float*)d_in[9];
    const float* pro_b_in  = (const float*)d_in[10];
    const float* pro_ws    = (const float*)d_in[11];
    const float* pro_w_out = (const float*)d_in[12];
    const float* pro_b_out = (const float*)d_in[13];
    const float* w_fc1     = (const float*)d_in[14];
    const float* b_fc1     = (const float*)d_in[15];
    const float* w_fc2     = (const float*)d_in[16];
    const float* b_fc2     = (const float*)d_in[17];
    const float* w_o       = (const float*)d_in[18];
    const float* b_o       = (const float*)d_in[19];
    float* out = (float*)d_out;

    float* h0m  = (float*)sym(g_h0m);
    float* prvm = (float*)sym(g_prvm);
    float* h0p  = (float*)sym(g_h0p);
    float* prvp = (float*)sym(g_prvp);
    float* supp = (float*)sym(g_supp);
    float* cat  = (float*)sym(g_cat);
    float* fc1  = (float*)sym(g_fc1);
    float* fc2  = (float*)sym(g_fc2);
    float* xm   = (float*)sym(g_xm);
    float* xp   = (float*)sym(g_xp);
    float* wts  = (float*)sym(g_wts);
    int*   cnt  = (int*)sym(g_cnt);
    int*   cur  = (int*)sym(g_cur);
    int*   offm = (int*)sym(g_offm);
    int*   offp = (int*)sym(g_offp);
    int*   cscm = (int*)sym(g_cscm);
    int*   cscp = (int*)sym(g_cscp);
    float* dism = (float*)sym(g_dism);
    float* disp = (float*)sym(g_disp);

    const int N = NN_NODES;

    // allow >48KB dynamic smem on the GEMM instantiations (host-side, not captured)
    cudaFuncSetAttribute(gemm_tf32_k<0, true>,  cudaFuncAttributeMaxDynamicSharedMemorySize, SMEM_BYTES);
    cudaFuncSetAttribute(gemm_tf32_k<0, false>, cudaFuncAttributeMaxDynamicSharedMemorySize, SMEM_BYTES);
    cudaFuncSetAttribute(gemm_tf32_k<1, true>,  cudaFuncAttributeMaxDynamicSharedMemorySize, SMEM_BYTES);
    cudaFuncSetAttribute(gemm_tf32_k<2, true>,  cudaFuncAttributeMaxDynamicSharedMemorySize, SMEM_BYTES);

    // ---- CSC build: mol ----
    zero_i_k<<<(N + 255) / 256, 256>>>(cnt, N);
    count_k<<<(E_MOL + 255) / 256, 256>>>(mol_ei + E_MOL, E_MOL, cnt);
    scan_k<<<1, 1024>>>(cnt, offm, cur, dism, N);
    scatter_k<<<(E_MOL + 255) / 256, 256>>>(mol_ei, mol_ei + E_MOL, E_MOL, cur, cscm);
    // ---- CSC build: pro ----
    zero_i_k<<<(N + 255) / 256, 256>>>(cnt, N);
    count_k<<<(E_PRO + 255) / 256, 256>>>(pro_ei + E_PRO, E_PRO, cnt);
    scan_k<<<1, 1024>>>(cnt, offp, cur, disp, N);
    scatter_k<<<(E_PRO + 255) / 256, 256>>>(pro_ei, pro_ei + E_PRO, E_PRO, cur, cscp);

    // ---- pre-round inputs + weights into scratch ----
    auto pr = [](const float* in, float* out, int ri, int ci, int ro, int co) {
        int tot = ro * co;
        padround_k<<<(tot + 255) / 256, 256>>>(in, out, ri, ci, ro, co);
    };
    pr(mol_x, xm, N, 78, N, KM_PAD);
    pr(pro_x, xp, N, 54, N, KP_PAD);
    pr(mol_w_in, wts + WIN_M, 78, HID, KM_PAD, HID);
    pr(pro_w_in, wts + WIN_P, 54, HID, KP_PAD, HID);
    pr(mol_ws, wts + WS_M, LAYERS * HID, HID, LAYERS * HID, HID);
    pr(pro_ws, wts + WS_P, LAYERS * HID, HID, LAYERS * HID, HID);
    pr(mol_w_out, wts + WOUT_M, HID, OUT_D, HID, OUT_D);
    pr(pro_w_out, wts + WOUT_P, HID, OUT_D, HID, OUT_D);
    pr(w_fc1, wts + WFC1, 256, 1024, 256, 1024);
    pr(w_fc2, wts + WFC2, 1024, 512, 1024, 512);

    // ---- input projections: h = relu(x W + b), dual-write h0 and prev ----
    {
        dim3 grid(HID / TBN, N / TBM);
        gemm_tf32_k<0, true><<<grid, 256, SMEM_BYTES>>>(xm, KM_PAD, wts + WIN_M, HID,
                                                        mol_b_in, nullptr, h0m, prvm, KM_PAD, HID, 0);
        gemm_tf32_k<0, true><<<grid, 256, SMEM_BYTES>>>(xp, KP_PAD, wts + WIN_P, HID,
                                                        pro_b_in, nullptr, h0p, prvp, KP_PAD, HID, 0);
    }

    // ---- GCNII layers ----
    dim3 gridL(HID / TBN, N / TBM);
    for (int l = 0; l < LAYERS; l++) {
        spmm_support_k<<<N, 128>>>(prvm, h0m, supp, offm, cscm, dism);
        gemm_tf32_k<1, true><<<gridL, 256, SMEM_BYTES>>>(supp, HID, wts + WS_M + l * HID * HID, HID,
                                                         nullptr, supp, prvm, nullptr, HID, HID, 0);
    }
    for (int l = 0; l < LAYERS; l++) {
        spmm_support_k<<<N, 128>>>(prvp, h0p, supp, offp, cscp, disp);
        gemm_tf32_k<1, true><<<gridL, 256, SMEM_BYTES>>>(supp, HID, wts + WS_P + l * HID * HID, HID,
                                                         nullptr, supp, prvp, nullptr, HID, HID, 0);
    }

    // ---- output projections into concat buffer [N, 256] ----
    {
        dim3 grid(OUT_D / TBN, N / TBM);
        gemm_tf32_k<2, true><<<grid, 256, SMEM_BYTES>>>(prvm, HID, wts + WOUT_M, OUT_D,
                                                        mol_b_out, nullptr, cat, nullptr, HID, 256, 0);
        gemm_tf32_k<2, true><<<grid, 256, SMEM_BYTES>>>(prvp, HID, wts + WOUT_P, OUT_D,
                                                        pro_b_out, nullptr, cat, nullptr, HID, 256, OUT_D);
    }

    // ---- MLP head ----
    {
        dim3 grid(1024 / TBN, N / TBM);
        gemm_tf32_k<0, true><<<grid, 256, SMEM_BYTES>>>(cat, 256, wts + WFC1, 1024,
                                                        b_fc1, nullptr, fc1, nullptr, 256, 1024, 0);
    }
    {
        dim3 grid(512 / TBN, N / TBM);
        gemm_tf32_k<0, false><<<grid, 256, SMEM_BYTES>>>(fc1, 1024, wts + WFC2, 512,
                                                         b_fc2, nullptr, fc2, nullptr, 1024, 512, 0);
    }
    gemv_k<<<N / 4, 128>>>(fc2, w_o, b_o, out);
}

// round 4
// speedup vs baseline: 1.8262x; 1.1817x over previous
#include <cuda_runtime.h>
#include <cstdint>

// Problem constants
#define NN_NODES 32768
#define E_MOL    131072
#define E_PRO    196608
#define HID      512
#define OUT_D    128
#define LAYERS   3
#define KM_PAD   96
#define KP_PAD   64

// ---------------- scratch (device globals) -----------------------------------
__device__ float g_h0m [NN_NODES * HID];
__device__ float g_prvm[NN_NODES * HID];
__device__ float g_h0p [NN_NODES * HID];
__device__ float g_prvp[NN_NODES * HID];
__device__ float g_supp[NN_NODES * HID];
__device__ float g_cat [NN_NODES * 256];
__device__ float g_fc1 [NN_NODES * 1024];
__device__ float g_fc2 [NN_NODES * 512];
__device__ float g_xm  [NN_NODES * KM_PAD];
__device__ float g_xp  [NN_NODES * KP_PAD];
__device__ float g_wts [2600000];          // transposed + tf32-rounded weights

// transposed weight offsets (all [N, Kpad] row-major)
#define WIN_M  0
#define WIN_P  49152
#define WS_M   81920
#define WS_P   868352
#define WOUT_M 1654784
#define WOUT_P 1720320
#define WFC1   1785856
#define WFC2   2048000

__device__ int   g_cnt [NN_NODES];
__device__ int   g_cur [NN_NODES];
__device__ int   g_offm[NN_NODES + 1];
__device__ int   g_offp[NN_NODES + 1];
__device__ int   g_cscm[E_MOL];
__device__ int   g_cscp[E_PRO];
__device__ float g_dism[NN_NODES];
__device__ float g_disp[NN_NODES];

// ---------------- helpers -----------------------------------------------------
__device__ __forceinline__ float tf32r(float f) {
    uint32_t u;
    asm("cvt.rna.tf32.f32 %0, %1;" : "=r"(u) : "f"(f));
    return __uint_as_float(u);
}

__global__ void zero_i_k(int* p, int n) {
    int i = blockIdx.x * blockDim.x + threadIdx.x;
    if (i < n) p[i] = 0;
}

__global__ void count_k(const int* __restrict__ col, int E, int* __restrict__ cnt) {
    int e = blockIdx.x * blockDim.x + threadIdx.x;
    if (e < E) atomicAdd(&cnt[col[e]], 1);
}

__global__ void scan_k(const int* __restrict__ cnt, int* __restrict__ offs,
                       int* __restrict__ cur, float* __restrict__ dis, int n) {
    __shared__ int sh[1024];
    int t = threadIdx.x;
    int per = n >> 10;
    int base = t * per;
    int s = 0;
    for (int j = 0; j < per; j++) s += cnt[base + j];
    sh[t] = s;
    __syncthreads();
    for (int off = 1; off < 1024; off <<= 1) {
        int v = (t >= off) ? sh[t - off] : 0;
        __syncthreads();
        sh[t] += v;
        __syncthreads();
    }
    int run = sh[t] - s;
    for (int j = 0; j < per; j++) {
        int c = cnt[base + j];
        offs[base + j] = run;
        cur[base + j]  = run;
        dis[base + j]  = rsqrtf((float)(c + 1));
        run += c;
    }
    if (t == 1023) offs[n] = run;
}

__global__ void scatter_k(const int* __restrict__ row, const int* __restrict__ col,
                          int E, int* __restrict__ cur, int* __restrict__ src) {
    int e = blockIdx.x * blockDim.x + threadIdx.x;
    if (e < E) {
        int c = col[e];
        int p = atomicAdd(&cur[c], 1);
        src[p] = row[e];
    }
}

// pad+round activations: out[r,c] = (c<cin) ? tf32(in[r,c]) : 0
__global__ void padround_k(const float* __restrict__ in, float* __restrict__ out,
                           int cin, int rows, int cout) {
    int i = blockIdx.x * blockDim.x + threadIdx.x;
    int total = rows * cout;
    if (i >= total) return;
    int r = i / cout, c = i - r * cout;
    out[i] = (c < cin) ? tf32r(in[(size_t)r * cin + c]) : 0.f;
}

// transpose+pad+round weights: in [Kin, Nn] -> out [Nn, Kpad]; optional +I
__global__ void padround_t_k(const float* __restrict__ in, float* __restrict__ out,
                             int Kin, int Nn, int Kpad, int addI) {
    int i = blockIdx.x * blockDim.x + threadIdx.x;
    int total = Nn * Kpad;
    if (i >= total) return;
    int n = i / Kpad, k = i - n * Kpad;
    float v = 0.f;
    if (k < Kin) {
        v = in[(size_t)k * Nn + n];
        if (addI && k == n) v += 1.0f;
        v = tf32r(v);
    }
    out[i] = v;
}

// ---------------- SpMM + support fuse (tf32-rounded output) -------------------
__global__ void spmm_support_k(const float* __restrict__ prev, const float* __restrict__ h0,
                               float* __restrict__ sup,
                               const int* __restrict__ offs, const int* __restrict__ srcs,
                               const float* __restrict__ dis) {
    int i = blockIdx.x;
    int t = threadIdx.x;
    const float4* pv = (const float4*)prev;
    float di = dis[i];
    float4 p = pv[(size_t)i * 128 + t];
    float self = di * di;
    float4 acc = make_float4(self * p.x, self * p.y, self * p.z, self * p.w);
    int e0 = offs[i], e1 = offs[i + 1];
    for (int e = e0; e < e1; e++) {
        int s = srcs[e];
        float w = di * dis[s];
        float4 q = pv[(size_t)s * 128 + t];
        acc.x += w * q.x; acc.y += w * q.y; acc.z += w * q.z; acc.w += w * q.w;
    }
    float4 h = ((const float4*)h0)[(size_t)i * 128 + t];
    float4 o;
    o.x = tf32r(0.8f * acc.x + 0.2f * h.x);
    o.y = tf32r(0.8f * acc.y + 0.2f * h.y);
    o.z = tf32r(0.8f * acc.z + 0.2f * h.z);
    o.w = tf32r(0.8f * acc.w + 0.2f * h.w);
    ((float4*)sup)[(size_t)i * 128 + t] = o;
}

// ---------------- TF32 mma.sync GEMM with ldmatrix + 3-stage cp.async ---------
// C[M, Nn] = A[M,K] * Wt[Nn,K]^T ; A,Wt K-major, pre-rounded tf32, K%32==0.
// MODE 0: out = relu(acc + bias[n])
// MODE 1: out = relu(acc) + prev_in        (weights carry +I; GCNII residual)
// MODE 2: out = acc + bias[n]              (strided: ldo/ocol)
#define TBM 128
#define TBN 128
#define TILE_B 16384u
#define STAGE_B (2u * TILE_B)
#define GSMEM (3u * STAGE_B)     // 98304

__device__ __forceinline__ uint32_t s2u(const void* p) {
    uint32_t a;
    asm("{ .reg .u64 t; cvta.to.shared.u64 t, %1; cvt.u32.u64 %0, t; }" : "=r"(a) : "l"(p));
    return a;
}

__device__ __forceinline__ void cp16(uint32_t s, const float* g) {
    asm volatile("cp.async.cg.shared.global [%0], [%1], 16;" :: "r"(s), "l"(g));
}

__device__ __forceinline__ void mma_tf32(float* c, const uint32_t* a, const uint32_t* b) {
    asm volatile(
        "mma.sync.aligned.m16n8k8.row.col.f32.tf32.tf32.f32 "
        "{%0,%1,%2,%3}, {%4,%5,%6,%7}, {%8,%9}, {%0,%1,%2,%3};"
        : "+f"(c[0]), "+f"(c[1]), "+f"(c[2]), "+f"(c[3])
        : "r"(a[0]), "r"(a[1]), "r"(a[2]), "r"(a[3]), "r"(b[0]), "r"(b[1]));
}

#define LDSM4(r0, r1, r2, r3, a)                                                   \
    asm volatile("ldmatrix.sync.aligned.m8n8.x4.shared.b16 {%0,%1,%2,%3}, [%4];"   \
                 : "=r"(r0), "=r"(r1), "=r"(r2), "=r"(r3) : "r"(a))

template <int MODE, bool ROUND>
__global__ __launch_bounds__(256, 2)
void gemm_tf32_k(const float* __restrict__ A, int lda,
                 const float* __restrict__ Wt, int ldb,
                 const float* __restrict__ bias, const float* __restrict__ prev_in,
                 float* __restrict__ out,
                 int K, int ldo, int ocol) {
    extern __shared__ float smem[];
    uint32_t smemu = s2u(smem);

    int tid = threadIdx.x;
    int bm = blockIdx.y * TBM;
    int bn = blockIdx.x * TBN;
    int warp = tid >> 5, lane = tid & 31;
    int wm = (warp >> 2) * 64;
    int wn = (warp & 3) * 32;
    int g = lane >> 2, tig = lane & 3;

    int seg = lane >> 3, rl = lane & 7;
    int rtile = ((seg & 1) << 3) + rl;
    int kqa = seg >> 1;

    uint32_t arow[4], brow[2];
#pragma unroll
    for (int mi = 0; mi < 4; mi++) arow[mi] = (uint32_t)(wm + mi * 16 + rtile) * 128u;
#pragma unroll
    for (int nj = 0; nj < 2; nj++) brow[nj] = (uint32_t)(wn + nj * 16 + rtile) * 128u;

    float acc[4][4][4];
#pragma unroll
    for (int mi = 0; mi < 4; mi++)
#pragma unroll
        for (int ni = 0; ni < 4; ni++)
#pragma unroll
            for (int e = 0; e < 4; e++) acc[mi][ni][e] = 0.f;

    auto load_tile = [&](int kt, int st) {
        uint32_t sa = smemu + st * STAGE_B;
        uint32_t sb = sa + TILE_B;
        const float* Ab = A + (size_t)bm * lda + kt * 32;
        const float* Bb = Wt + (size_t)bn * ldb + kt * 32;
#pragma unroll
        for (int it = 0; it < 4; it++) {
            int idx = it * 256 + tid;
            int row = idx >> 3, q = idx & 7;
            uint32_t sw = (uint32_t)row * 128u + (uint32_t)((q ^ (row & 7)) << 4);
            cp16(sa + sw, Ab + (size_t)row * lda + q * 4);
        }
#pragma unroll
        for (int it = 0; it < 4; it++) {
            int idx = it * 256 + tid;
            int row = idx >> 3, q = idx & 7;
            uint32_t sw = (uint32_t)row * 128u + (uint32_t)((q ^ (row & 7)) << 4);
            cp16(sb + sw, Bb + (size_t)row * ldb + q * 4);
        }
        asm volatile("cp.async.commit_group;" ::: "memory");
    };

    int nk = K >> 5;
    load_tile(0, 0);
    if (nk > 1) load_tile(1, 1);

    for (int kt = 0; kt < nk; kt++) {
        if (kt < nk - 1) asm volatile("cp.async.wait_group 1;" ::: "memory");
        else             asm volatile("cp.async.wait_group 0;" ::: "memory");
        __syncthreads();
        if (kt + 2 < nk) load_tile(kt + 2, (kt + 2) % 3);

        uint32_t sa = smemu + (kt % 3) * STAGE_B;
        uint32_t sb = sa + TILE_B;
#pragma unroll
        for (int ks = 0; ks < 4; ks++) {
            uint32_t kx = (uint32_t)(((ks * 2 + kqa) ^ rl) << 4);
            uint32_t af[4][4], bf[4][2];
#pragma unroll
            for (int mi = 0; mi < 4; mi++)
                LDSM4(af[mi][0], af[mi][1], af[mi][2], af[mi][3], sa + arow[mi] + kx);
#pragma unroll
            for (int nj = 0; nj < 2; nj++)
                LDSM4(bf[2 * nj][0], bf[2 * nj + 1][0], bf[2 * nj][1], bf[2 * nj + 1][1],
                      sb + brow[nj] + kx);
#pragma unroll
            for (int mi = 0; mi < 4; mi++)
#pragma unroll
                for (int ni = 0; ni < 4; ni++) mma_tf32(acc[mi][ni], af[mi], bf[ni]);
        }
        __syncthreads();
    }

#pragma unroll
    for (int mi = 0; mi < 4; mi++)
#pragma unroll
        for (int ni = 0; ni < 4; ni++) {
            int r = bm + wm + mi * 16 + g;
            int c = bn + wn + ni * 8 + 2 * tig;
#pragma unroll
            for (int e = 0; e < 4; e++) {
                int rr = r + ((e >= 2) ? 8 : 0);
                int cc = c + (e & 1);
                float v = acc[mi][ni][e];
                if (MODE == 0 || MODE == 2) {
                    v += bias[cc];
                    if (MODE == 0) v = fmaxf(v, 0.f);
                    if (ROUND) v = tf32r(v);
                    out[(size_t)rr * ldo + ocol + cc] = v;
                } else {
                    size_t idx = (size_t)rr * ldo + cc;
                    v = fmaxf(v, 0.f) + prev_in[idx];
                    if (ROUND) v = tf32r(v);
                    out[idx] = v;
                }
            }
        }
}

// ---------------- final GEMV --------------------------------------------------
__global__ void gemv_k(const float* __restrict__ X, const float* __restrict__ w,
                       const float* __restrict__ b, float* __restrict__ out) {
    int row = blockIdx.x * 4 + (threadIdx.x >> 5);
    int lane = threadIdx.x & 31;
    const float* x = X + (size_t)row * 512;
    float s = 0.f;
#pragma unroll
    for (int j = 0; j < 16; j++) s += x[lane + j * 32] * w[lane + j * 32];
#pragma unroll
    for (int o = 16; o > 0; o >>= 1) s += __shfl_xor_sync(0xFFFFFFFFu, s, o);
    if (lane == 0) out[row] = s + b[0];
}

// ---------------- launch ------------------------------------------------------
static void* sym(const void* s) {
    void* p = nullptr;
    cudaGetSymbolAddress(&p, (const void*)s);
    return p;
}

extern "C" void kernel_launch(void* const* d_in, const int* in_sizes, int n_in,
                              void* d_out, int out_size) {
    const float* mol_x     = (const float*)d_in[0];
    const int*   mol_ei    = (const int*)d_in[1];
    const float* pro_x     = (const float*)d_in[2];
    const int*   pro_ei    = (const int*)d_in[3];
    const float* mol_w_in  = (const float*)d_in[4];
    const float* mol_b_in  = (const float*)d_in[5];
    const float* mol_ws    = (const float*)d_in[6];
    const float* mol_w_out = (const float*)d_in[7];
    const float* mol_b_out = (const float*)d_in[8];
    const float* pro_w_in  = (const float*)d_in[9];
    const float* pro_b_in  = (const float*)d_in[10];
    const float* pro_ws    = (const float*)d_in[11];
    const float* pro_w_out = (const float*)d_in[12];
    const float* pro_b_out = (const float*)d_in[13];
    const float* w_fc1     = (const float*)d_in[14];
    const float* b_fc1     = (const float*)d_in[15];
    const float* w_fc2     = (const float*)d_in[16];
    const float* b_fc2     = (const float*)d_in[17];
    const float* w_o       = (const float*)d_in[18];
    const float* b_o       = (const float*)d_in[19];
    float* out = (float*)d_out;

    float* h0m  = (float*)sym(g_h0m);
    float* prvm = (float*)sym(g_prvm);
    float* h0p  = (float*)sym(g_h0p);
    float* prvp = (float*)sym(g_prvp);
    float* supp = (float*)sym(g_supp);
    float* cat  = (float*)sym(g_cat);
    float* fc1  = (float*)sym(g_fc1);
    float* fc2  = (float*)sym(g_fc2);
    float* xm   = (float*)sym(g_xm);
    float* xp   = (float*)sym(g_xp);
    float* wts  = (float*)sym(g_wts);
    int*   cnt  = (int*)sym(g_cnt);
    int*   cur  = (int*)sym(g_cur);
    int*   offm = (int*)sym(g_offm);
    int*   offp = (int*)sym(g_offp);
    int*   cscm = (int*)sym(g_cscm);
    int*   cscp = (int*)sym(g_cscp);
    float* dism = (float*)sym(g_dism);
    float* disp = (float*)sym(g_disp);

    const int N = NN_NODES;

    cudaFuncSetAttribute(gemm_tf32_k<0, true>,  cudaFuncAttributeMaxDynamicSharedMemorySize, GSMEM);
    cudaFuncSetAttribute(gemm_tf32_k<0, false>, cudaFuncAttributeMaxDynamicSharedMemorySize, GSMEM);
    cudaFuncSetAttribute(gemm_tf32_k<1, true>,  cudaFuncAttributeMaxDynamicSharedMemorySize, GSMEM);
    cudaFuncSetAttribute(gemm_tf32_k<2, true>,  cudaFuncAttributeMaxDynamicSharedMemorySize, GSMEM);

    // ---- CSC build ----
    zero_i_k<<<(N + 255) / 256, 256>>>(cnt, N);
    count_k<<<(E_MOL + 255) / 256, 256>>>(mol_ei + E_MOL, E_MOL, cnt);
    scan_k<<<1, 1024>>>(cnt, offm, cur, dism, N);
    scatter_k<<<(E_MOL + 255) / 256, 256>>>(mol_ei, mol_ei + E_MOL, E_MOL, cur, cscm);
    zero_i_k<<<(N + 255) / 256, 256>>>(cnt, N);
    count_k<<<(E_PRO + 255) / 256, 256>>>(pro_ei + E_PRO, E_PRO, cnt);
    scan_k<<<1, 1024>>>(cnt, offp, cur, disp, N);
    scatter_k<<<(E_PRO + 255) / 256, 256>>>(pro_ei, pro_ei + E_PRO, E_PRO, cur, cscp);

    // ---- pad+round activations; transpose+pad+round weights ----
    padround_k<<<(N * KM_PAD + 255) / 256, 256>>>(mol_x, xm, 78, N, KM_PAD);
    padround_k<<<(N * KP_PAD + 255) / 256, 256>>>(pro_x, xp, 54, N, KP_PAD);
    auto prt = [](const float* in, float* o, int Kin, int Nn, int Kpad, int addI) {
        int tot = Nn * Kpad;
        padround_t_k<<<(tot + 255) / 256, 256>>>(in, o, Kin, Nn, Kpad, addI);
    };
    prt(mol_w_in, wts + WIN_M, 78, HID, KM_PAD, 0);
    prt(pro_w_in, wts + WIN_P, 54, HID, KP_PAD, 0);
    for (int l = 0; l < LAYERS; l++) {
        prt(mol_ws + (size_t)l * HID * HID, wts + WS_M + (size_t)l * HID * HID, HID, HID, HID, 1);
        prt(pro_ws + (size_t)l * HID * HID, wts + WS_P + (size_t)l * HID * HID, HID, HID, HID, 1);
    }
    prt(mol_w_out, wts + WOUT_M, HID, OUT_D, HID, 0);
    prt(pro_w_out, wts + WOUT_P, HID, OUT_D, HID, 0);
    prt(w_fc1, wts + WFC1, 256, 1024, 256, 0);
    prt(w_fc2, wts + WFC2, 1024, 512, 1024, 0);

    const int GY = N / TBM;   // 256

    // ---- input projections: h0 = relu(x W + b) ----
    gemm_tf32_k<0, true><<<dim3(HID / TBN, GY), 256, GSMEM>>>(
        xm, KM_PAD, wts + WIN_M, KM_PAD, mol_b_in, nullptr, h0m, KM_PAD, HID, 0);
    gemm_tf32_k<0, true><<<dim3(HID / TBN, GY), 256, GSMEM>>>(
        xp, KP_PAD, wts + WIN_P, KP_PAD, pro_b_in, nullptr, h0p, KP_PAD, HID, 0);

    // ---- GCNII layers: prev_new = relu(S(I+W)) + prev ----
    for (int l = 0; l < LAYERS; l++) {
        const float* pin = (l == 0) ? h0m : prvm;
        spmm_support_k<<<N, 128>>>(pin, h0m, supp, offm, cscm, dism);
        gemm_tf32_k<1, true><<<dim3(HID / TBN, GY), 256, GSMEM>>>(
            supp, HID, wts + WS_M + (size_t)l * HID * HID, HID,
            nullptr, pin, prvm, HID, HID, 0);
    }
    for (int l = 0; l < LAYERS; l++) {
        const float* pin = (l == 0) ? h0p : prvp;
        spmm_support_k<<<N, 128>>>(pin, h0p, supp, offp, cscp, disp);
        gemm_tf32_k<1, true><<<dim3(HID / TBN, GY), 256, GSMEM>>>(
            supp, HID, wts + WS_P + (size_t)l * HID * HID, HID,
            nullptr, pin, prvp, HID, HID, 0);
    }

    // ---- output projections into concat buffer [N, 256] ----
    gemm_tf32_k<2, true><<<dim3(OUT_D / TBN, GY), 256, GSMEM>>>(
        prvm, HID, wts + WOUT_M, HID, mol_b_out, nullptr, cat, HID, 256, 0);
    gemm_tf32_k<2, true><<<dim3(OUT_D / TBN, GY), 256, GSMEM>>>(
        prvp, HID, wts + WOUT_P, HID, pro_b_out, nullptr, cat, HID, 256, OUT_D);

    // ---- MLP head ----
    gemm_tf32_k<0, true><<<dim3(1024 / TBN, GY), 256, GSMEM>>>(
        cat, 256, wts + WFC1, 256, b_fc1, nullptr, fc1, 256, 1024, 0);
    gemm_tf32_k<0, false><<<dim3(512 / TBN, GY), 256, GSMEM>>>(
        fc1, 1024, wts + WFC2, 1024, b_fc2, nullptr, fc2, 1024, 512, 0);
    gemv_k<<<N / 4, 128>>>(fc2, w_o, b_o, out);
}